// round 1
// baseline (speedup 1.0000x reference)
#include <cuda_runtime.h>
#include <cstdint>

// Problem constants
#define BB   2
#define SS   4096
#define DD   2048
#define HH   16
#define HD   128
#define CHUNK 64
#define NC   (SS / CHUNK)          // 64 chunks
#define MROWS (BB * SS)            // 8192
#define NBH  (BB * HH)             // 32
#define QSCALE 0.08838834764831845f  // 128^-0.5

// ---------------- scratch (device globals; no allocations allowed) ----------
__device__ float g_Q[(size_t)MROWS * DD];
__device__ float g_K[(size_t)MROWS * DD];
__device__ float g_V[(size_t)MROWS * DD];
__device__ float g_O[(size_t)MROWS * DD];
__device__ float g_KV[(size_t)NBH * NC * HD * HD];   // per-chunk KV, then exclusive prefix S

// ---------------- GEMM: C[M,N] = alpha * A[M,K] @ B[N,K]^T (all row-major) --
#define BM 128
#define BN 128
#define BK 16
#define TM 8
#define TN 8

__global__ __launch_bounds__(256) void gemm_nt(const float* __restrict__ A,
                                               const float* __restrict__ B,
                                               float* __restrict__ C,
                                               int M, int N, int K, float alpha) {
    __shared__ float As[BK][BM];
    __shared__ float Bs[BK][BN];
    const int t  = threadIdx.x;
    const int tn = (t & 15) * TN;
    const int tm = (t >> 4) * TM;
    const float* Ab = A + (size_t)blockIdx.y * BM * K;
    const float* Bb = B + (size_t)blockIdx.x * BN * K;

    float acc[TM][TN];
    #pragma unroll
    for (int i = 0; i < TM; i++)
        #pragma unroll
        for (int j = 0; j < TN; j++) acc[i][j] = 0.f;

    for (int k0 = 0; k0 < K; k0 += BK) {
        #pragma unroll
        for (int jj = 0; jj < 2; jj++) {
            int f   = t + jj * 256;       // float4 index 0..511
            int row = f >> 2;             // 0..127
            int c4  = (f & 3) * 4;        // 0,4,8,12
            float4 a = *(const float4*)(Ab + (size_t)row * K + k0 + c4);
            As[c4 + 0][row] = a.x; As[c4 + 1][row] = a.y;
            As[c4 + 2][row] = a.z; As[c4 + 3][row] = a.w;
            float4 b = *(const float4*)(Bb + (size_t)row * K + k0 + c4);
            Bs[c4 + 0][row] = b.x; Bs[c4 + 1][row] = b.y;
            Bs[c4 + 2][row] = b.z; Bs[c4 + 3][row] = b.w;
        }
        __syncthreads();
        #pragma unroll
        for (int kk = 0; kk < BK; kk++) {
            float ra[TM], rb[TN];
            #pragma unroll
            for (int i = 0; i < TM; i += 4) {
                float4 v = *(const float4*)&As[kk][tm + i];
                ra[i] = v.x; ra[i + 1] = v.y; ra[i + 2] = v.z; ra[i + 3] = v.w;
            }
            #pragma unroll
            for (int j = 0; j < TN; j += 4) {
                float4 v = *(const float4*)&Bs[kk][tn + j];
                rb[j] = v.x; rb[j + 1] = v.y; rb[j + 2] = v.z; rb[j + 3] = v.w;
            }
            #pragma unroll
            for (int i = 0; i < TM; i++)
                #pragma unroll
                for (int j = 0; j < TN; j++)
                    acc[i][j] += ra[i] * rb[j];
        }
        __syncthreads();
    }

    float* Cb = C + (size_t)(blockIdx.y * BM + tm) * N + blockIdx.x * BN + tn;
    #pragma unroll
    for (int i = 0; i < TM; i++) {
        #pragma unroll
        for (int j = 0; j < TN; j += 4) {
            float4 v;
            v.x = alpha * acc[i][j];     v.y = alpha * acc[i][j + 1];
            v.z = alpha * acc[i][j + 2]; v.w = alpha * acc[i][j + 3];
            *(float4*)(Cb + (size_t)i * N + j) = v;
        }
    }
}

// ---------------- per-chunk KV = K_c^T V_c  ([HD,HD] per (b,h,chunk)) ------
#define PAD (HD + 1)   // 129, conflict-free strided smem access

__global__ __launch_bounds__(256) void kv_kernel(float* __restrict__ KVout) {
    extern __shared__ float sm[];
    float* ks = sm;                 // CHUNK * PAD
    float* vs = sm + CHUNK * PAD;
    const int blk = blockIdx.x;     // bh*NC + c
    const int bh = blk / NC, c = blk % NC;
    const int b = bh / HH, h = bh % HH;
    const size_t base = ((size_t)(b * SS + c * CHUNK)) * DD + (size_t)h * HD;
    const int t = threadIdx.x;

    for (int i = t; i < CHUNK * HD; i += 256) {
        int s = i / HD, d = i % HD;
        ks[s * PAD + d] = g_K[base + (size_t)s * DD + d];
        vs[s * PAD + d] = g_V[base + (size_t)s * DD + d];
    }
    __syncthreads();

    const int e  = t & (HD - 1);          // 0..127
    const int d0 = (t >> 7) * 64;         // 0 or 64
    float acc[64];
    #pragma unroll
    for (int d = 0; d < 64; d++) acc[d] = 0.f;

    for (int s = 0; s < CHUNK; s++) {
        float vv = vs[s * PAD + e];
        #pragma unroll
        for (int d = 0; d < 64; d++)
            acc[d] += ks[s * PAD + d0 + d] * vv;   // ks broadcast across lanes
    }
    float* out = KVout + (size_t)blk * HD * HD;
    #pragma unroll 4
    for (int d = 0; d < 64; d++)
        out[(size_t)(d0 + d) * HD + e] = acc[d];
}

// ---------------- exclusive prefix over chunks (in place) ------------------
__global__ __launch_bounds__(256) void scan_kernel(float* __restrict__ KV) {
    size_t g = (size_t)blockIdx.x * blockDim.x + threadIdx.x; // 0..NBH*HD*HD-1
    int bh = (int)(g / (HD * HD));
    int de = (int)(g % (HD * HD));
    float* p = KV + ((size_t)bh * NC) * HD * HD + de;
    float acc = 0.f;
    for (int c = 0; c < NC; c++) {
        float tmp = p[(size_t)c * HD * HD];
        p[(size_t)c * HD * HD] = acc;
        acc += tmp;
    }
}

// ---------------- per-chunk attention: o = tril(q k^T) v + q S -------------
__global__ __launch_bounds__(256) void attn_kernel(const float* __restrict__ Sg) {
    extern __shared__ float sm[];
    float* qs = sm;                         // CHUNK * PAD
    float* ks = qs + CHUNK * PAD;
    float* vs = ks + CHUNK * PAD;
    float* at = vs + CHUNK * PAD;           // CHUNK * (CHUNK+1)
    const int APAD = CHUNK + 1;

    const int blk = blockIdx.x;             // bh*NC + c
    const int bh = blk / NC, c = blk % NC;
    const int b = bh / HH, h = bh % HH;
    const size_t base = ((size_t)(b * SS + c * CHUNK)) * DD + (size_t)h * HD;
    const int t = threadIdx.x;

    for (int i = t; i < CHUNK * HD; i += 256) {
        int s = i / HD, d = i % HD;
        qs[s * PAD + d] = g_Q[base + (size_t)s * DD + d];
        ks[s * PAD + d] = g_K[base + (size_t)s * DD + d];
        vs[s * PAD + d] = g_V[base + (size_t)s * DD + d];
    }
    __syncthreads();

    // attn[cc][ss] = (ss<=cc) ? q[cc].k[ss] : 0
    for (int i = t; i < CHUNK * CHUNK; i += 256) {
        int cc = i / CHUNK, ss = i % CHUNK;
        float acc = 0.f;
        if (ss <= cc) {
            #pragma unroll 8
            for (int d = 0; d < HD; d++)
                acc += qs[cc * PAD + d] * ks[ss * PAD + d];
        }
        at[cc * APAD + ss] = acc;
    }
    __syncthreads();

    const int e  = t & (HD - 1);     // column 0..127
    const int r0 = (t >> 7) * 32;    // 32 rows per thread
    float o[32];
    #pragma unroll
    for (int r = 0; r < 32; r++) o[r] = 0.f;

    // intra-chunk
    for (int s = 0; s < CHUNK; s++) {
        float vv = vs[s * PAD + e];
        #pragma unroll
        for (int r = 0; r < 32; r++)
            o[r] += at[(r0 + r) * APAD + s] * vv;
    }
    // inter-chunk: q @ S   (S streamed from gmem through L2)
    const float* Sb = Sg + (size_t)blk * HD * HD;
    #pragma unroll 4
    for (int d = 0; d < HD; d++) {
        float sv = Sb[(size_t)d * HD + e];
        #pragma unroll
        for (int r = 0; r < 32; r++)
            o[r] += qs[(r0 + r) * PAD + d] * sv;
    }
    #pragma unroll
    for (int r = 0; r < 32; r++)
        g_O[base + (size_t)(r0 + r) * DD + e] = o[r];
}

// ---------------------------------------------------------------------------
extern "C" void kernel_launch(void* const* d_in, const int* in_sizes, int n_in,
                              void* d_out, int out_size) {
    const float* x  = (const float*)d_in[0];
    const float* Wq = (const float*)d_in[1];
    const float* Wk = (const float*)d_in[2];
    const float* Wv = (const float*)d_in[3];
    const float* Wo = (const float*)d_in[4];
    float* out = (float*)d_out;

    float *pQ, *pK, *pV, *pO, *pKV;
    cudaGetSymbolAddress((void**)&pQ,  g_Q);
    cudaGetSymbolAddress((void**)&pK,  g_K);
    cudaGetSymbolAddress((void**)&pV,  g_V);
    cudaGetSymbolAddress((void**)&pO,  g_O);
    cudaGetSymbolAddress((void**)&pKV, g_KV);

    const int ATTN_SMEM = (3 * CHUNK * PAD + CHUNK * (CHUNK + 1)) * (int)sizeof(float);
    const int KV_SMEM   = (2 * CHUNK * PAD) * (int)sizeof(float);
    cudaFuncSetAttribute(attn_kernel, cudaFuncAttributeMaxDynamicSharedMemorySize, ATTN_SMEM);
    cudaFuncSetAttribute(kv_kernel,   cudaFuncAttributeMaxDynamicSharedMemorySize, KV_SMEM);

    dim3 ggrid(DD / BN, MROWS / BM);   // (16, 64)

    gemm_nt<<<ggrid, 256>>>(x, Wq, pQ, MROWS, DD, DD, QSCALE);
    gemm_nt<<<ggrid, 256>>>(x, Wk, pK, MROWS, DD, DD, 1.f);
    gemm_nt<<<ggrid, 256>>>(x, Wv, pV, MROWS, DD, DD, 1.f);

    kv_kernel<<<NBH * NC, 256, KV_SMEM>>>(pKV);
    scan_kernel<<<(NBH * HD * HD) / 256, 256>>>(pKV);
    attn_kernel<<<NBH * NC, 256, ATTN_SMEM>>>(pKV);

    gemm_nt<<<ggrid, 256>>>(pO, Wo, out, MROWS, DD, DD, 1.f);
    (void)in_sizes; (void)n_in; (void)out_size;
}

// round 6
// speedup vs baseline: 2.5753x; 2.5753x over previous
#include <cuda_runtime.h>
#include <cuda_bf16.h>
#include <cstdint>

// ---------------- problem constants ----------------
#define BB   2
#define SS   4096
#define DD   2048
#define HH   16
#define HD   128
#define CHUNK 64
#define NC   (SS / CHUNK)          // 64 chunks
#define MROWS (BB * SS)            // 8192
#define NBH  (BB * HH)             // 32
#define QSCALE 0.08838834764831845f  // 128^-0.5
#define WSZ  (DD * DD)

// ---------------- scratch (device globals; no allocations allowed) ---------
__device__ float g_Q[(size_t)MROWS * DD];
__device__ float g_K[(size_t)MROWS * DD];
__device__ float g_V[(size_t)MROWS * DD];
__device__ float g_O[(size_t)MROWS * DD];
__device__ float g_KV[(size_t)NBH * NC * HD * HD];

__device__ __align__(256) __nv_bfloat16 g_xhi[(size_t)MROWS * DD];
__device__ __align__(256) __nv_bfloat16 g_xlo[(size_t)MROWS * DD];
__device__ __align__(256) __nv_bfloat16 g_ohi[(size_t)MROWS * DD];
__device__ __align__(256) __nv_bfloat16 g_olo[(size_t)MROWS * DD];
__device__ __align__(256) __nv_bfloat16 g_whi[(size_t)4 * WSZ];
__device__ __align__(256) __nv_bfloat16 g_wlo[(size_t)4 * WSZ];

// ================= fp32 -> bf16 hi/lo split =================
__device__ __forceinline__ uint32_t pk2(float a, float b) {
    __nv_bfloat162 t = __floats2bfloat162_rn(a, b);
    return *(uint32_t*)&t;
}

__global__ __launch_bounds__(256) void cvt_kernel(const float* __restrict__ src,
                                                  __nv_bfloat16* __restrict__ hi,
                                                  __nv_bfloat16* __restrict__ lo) {
    size_t i = (size_t)blockIdx.x * 256 + threadIdx.x;
    float4 v = ((const float4*)src)[i];
    float h0 = __bfloat162float(__float2bfloat16(v.x));
    float h1 = __bfloat162float(__float2bfloat16(v.y));
    float h2 = __bfloat162float(__float2bfloat16(v.z));
    float h3 = __bfloat162float(__float2bfloat16(v.w));
    uint2 H, L;
    H.x = pk2(h0, h1);           H.y = pk2(h2, h3);
    L.x = pk2(v.x - h0, v.y - h1); L.y = pk2(v.z - h2, v.w - h3);
    ((uint2*)hi)[i] = H;
    ((uint2*)lo)[i] = L;
}

// ================= mma.sync bf16 hi/lo GEMM =================
// C[M,N] = alpha * (Ahi+Alo)[M,K] @ (Bhi+Blo)[N,K]^T  (lo*lo dropped)
#define STAGES 3
#define STAGE_BYTES 65536           // 4 planes x 128 rows x 128B
#define KITERS (DD / 64)            // 32
#define GEMM_SMEM (STAGES * STAGE_BYTES)   // 196608

__device__ __forceinline__ uint32_t smem_u32(const void* p) {
    return (uint32_t)__cvta_generic_to_shared(p);
}
__device__ __forceinline__ void cp16(uint32_t d, const void* s) {
    asm volatile("cp.async.cg.shared.global [%0], [%1], 16;\n" :: "r"(d), "l"(s));
}
__device__ __forceinline__ void ldsm4(uint32_t* r, uint32_t a) {
    asm volatile("ldmatrix.sync.aligned.m8n8.x4.shared.b16 {%0,%1,%2,%3}, [%4];\n"
                 : "=r"(r[0]), "=r"(r[1]), "=r"(r[2]), "=r"(r[3]) : "r"(a));
}
__device__ __forceinline__ void mma_bf16(float* c, const uint32_t* a, const uint32_t* b) {
    asm volatile("mma.sync.aligned.m16n8k16.row.col.f32.bf16.bf16.f32 "
                 "{%0,%1,%2,%3}, {%4,%5,%6,%7}, {%8,%9}, {%0,%1,%2,%3};\n"
                 : "+f"(c[0]), "+f"(c[1]), "+f"(c[2]), "+f"(c[3])
                 : "r"(a[0]), "r"(a[1]), "r"(a[2]), "r"(a[3]), "r"(b[0]), "r"(b[1]));
}

__device__ __forceinline__ void issue_stage(uint32_t sbase,
                                            const __nv_bfloat16* __restrict__ Ahi,
                                            const __nv_bfloat16* __restrict__ Alo,
                                            const __nv_bfloat16* __restrict__ Bhi,
                                            const __nv_bfloat16* __restrict__ Blo,
                                            int k0, int tid) {
    const int r = tid >> 3, c = tid & 7;
    #pragma unroll
    for (int i = 0; i < 16; i++) {
        const int plane = i >> 2;
        const int row = (i & 3) * 32 + r;
        const __nv_bfloat16* src =
            (plane == 0 ? Ahi : plane == 1 ? Alo : plane == 2 ? Bhi : Blo)
            + (size_t)row * DD + k0 + c * 8;
        uint32_t dst = sbase + plane * 16384 + row * 128 + ((c ^ (row & 7)) << 4);
        cp16(dst, src);
    }
    asm volatile("cp.async.commit_group;\n" ::: "memory");
}

__device__ __forceinline__ void stage_compute(uint32_t sbase, int lane,
                                              int wm0, int wn0, float acc[4][4][4]) {
    const int arow_off   = (lane & 7) + ((lane >> 3) & 1) * 8;
    const int achunk_sel = lane >> 4;            // 0/1
    const int brow_off   = (lane & 7) + ((lane >> 4) << 3);
    const int bchunk_sel = (lane >> 3) & 1;
    #pragma unroll
    for (int ks = 0; ks < 4; ks++) {
        uint32_t ahi[4][4], alo[4][4];
        #pragma unroll
        for (int mf = 0; mf < 4; mf++) {
            int row = wm0 + mf * 16 + arow_off;
            int ch  = 2 * ks + achunk_sel;
            uint32_t off = (uint32_t)(row * 128 + ((ch ^ (row & 7)) << 4));
            ldsm4(ahi[mf], sbase + 0     + off);
            ldsm4(alo[mf], sbase + 16384 + off);
        }
        uint32_t bhi[2][4], blo[2][4];
        #pragma unroll
        for (int nf2 = 0; nf2 < 2; nf2++) {
            int row = wn0 + nf2 * 16 + brow_off;
            int ch  = 2 * ks + bchunk_sel;
            uint32_t off = (uint32_t)(row * 128 + ((ch ^ (row & 7)) << 4));
            ldsm4(bhi[nf2], sbase + 32768 + off);
            ldsm4(blo[nf2], sbase + 49152 + off);
        }
        #pragma unroll
        for (int mf = 0; mf < 4; mf++)
            #pragma unroll
            for (int nf = 0; nf < 4; nf++) {
                const uint32_t* bh = &bhi[nf >> 1][(nf & 1) * 2];
                const uint32_t* bl = &blo[nf >> 1][(nf & 1) * 2];
                mma_bf16(acc[mf][nf], ahi[mf], bh);   // hi*hi
                mma_bf16(acc[mf][nf], ahi[mf], bl);   // hi*lo
                mma_bf16(acc[mf][nf], alo[mf], bh);   // lo*hi
            }
    }
}

__global__ __launch_bounds__(256, 1) void gemm_mma(
        const __nv_bfloat16* __restrict__ Ahi, const __nv_bfloat16* __restrict__ Alo,
        const __nv_bfloat16* __restrict__ Bhi, const __nv_bfloat16* __restrict__ Blo,
        float* __restrict__ C, float alpha) {
    extern __shared__ char smc[];
    const uint32_t sb = smem_u32(smc);
    const int tid = threadIdx.x, lane = tid & 31, w = tid >> 5;
    const int bm0 = blockIdx.y * 128, bn0 = blockIdx.x * 128;
    const int wm0 = (w >> 2) * 64, wn0 = (w & 3) * 32;
    const __nv_bfloat16* At_hi = Ahi + (size_t)bm0 * DD;
    const __nv_bfloat16* At_lo = Alo + (size_t)bm0 * DD;
    const __nv_bfloat16* Bt_hi = Bhi + (size_t)bn0 * DD;
    const __nv_bfloat16* Bt_lo = Blo + (size_t)bn0 * DD;

    float acc[4][4][4];
    #pragma unroll
    for (int a = 0; a < 4; a++)
        #pragma unroll
        for (int b = 0; b < 4; b++)
            #pragma unroll
            for (int c = 0; c < 4; c++) acc[a][b][c] = 0.f;

    issue_stage(sb + 0 * STAGE_BYTES, At_hi, At_lo, Bt_hi, Bt_lo, 0,  tid);
    issue_stage(sb + 1 * STAGE_BYTES, At_hi, At_lo, Bt_hi, Bt_lo, 64, tid);

    for (int it = 0; it < KITERS; ++it) {
        if (it + 2 < KITERS) {
            asm volatile("cp.async.wait_group 1;\n" ::: "memory");
        } else {
            asm volatile("cp.async.wait_group 0;\n" ::: "memory");
        }
        __syncthreads();
        if (it + 2 < KITERS)
            issue_stage(sb + ((it + 2) % STAGES) * STAGE_BYTES,
                        At_hi, At_lo, Bt_hi, Bt_lo, (it + 2) * 64, tid);
        stage_compute(sb + (it % STAGES) * STAGE_BYTES, lane, wm0, wn0, acc);
        __syncthreads();
    }

    #pragma unroll
    for (int mf = 0; mf < 4; mf++)
        #pragma unroll
        for (int nf = 0; nf < 4; nf++) {
            int row = bm0 + wm0 + mf * 16 + (lane >> 2);
            int col = bn0 + wn0 + nf * 8 + (lane & 3) * 2;
            float2 v0 = make_float2(alpha * acc[mf][nf][0], alpha * acc[mf][nf][1]);
            float2 v1 = make_float2(alpha * acc[mf][nf][2], alpha * acc[mf][nf][3]);
            *(float2*)(C + (size_t)row * DD + col) = v0;
            *(float2*)(C + (size_t)(row + 8) * DD + col) = v1;
        }
}

// ---------------- per-chunk KV = K_c^T V_c ----------------
#define PAD (HD + 1)

__global__ __launch_bounds__(256) void kv_kernel(float* __restrict__ KVout) {
    extern __shared__ float smf[];
    float* ks = smf;
    float* vs = smf + CHUNK * PAD;
    const int blk = blockIdx.x;
    const int bh = blk / NC, c = blk % NC;
    const int b = bh / HH, h = bh % HH;
    const size_t base = ((size_t)(b * SS + c * CHUNK)) * DD + (size_t)h * HD;
    const int t = threadIdx.x;

    for (int i = t; i < CHUNK * HD; i += 256) {
        int s = i / HD, d = i % HD;
        ks[s * PAD + d] = g_K[base + (size_t)s * DD + d];
        vs[s * PAD + d] = g_V[base + (size_t)s * DD + d];
    }
    __syncthreads();

    const int e  = t & (HD - 1);
    const int d0 = (t >> 7) * 64;
    float acc[64];
    #pragma unroll
    for (int d = 0; d < 64; d++) acc[d] = 0.f;

    for (int s = 0; s < CHUNK; s++) {
        float vv = vs[s * PAD + e];
        #pragma unroll
        for (int d = 0; d < 64; d++)
            acc[d] += ks[s * PAD + d0 + d] * vv;
    }
    float* out = KVout + (size_t)blk * HD * HD;
    #pragma unroll 4
    for (int d = 0; d < 64; d++)
        out[(size_t)(d0 + d) * HD + e] = acc[d];
}

// ---------------- exclusive prefix over chunks ----------------
__global__ __launch_bounds__(256) void scan_kernel(float* __restrict__ KV) {
    size_t g = (size_t)blockIdx.x * blockDim.x + threadIdx.x;
    int bh = (int)(g / (HD * HD));
    int de = (int)(g % (HD * HD));
    float* p = KV + ((size_t)bh * NC) * HD * HD + de;
    float acc = 0.f;
    for (int c = 0; c < NC; c++) {
        float tmp = p[(size_t)c * HD * HD];
        p[(size_t)c * HD * HD] = acc;
        acc += tmp;
    }
}

// ---------------- per-chunk attention ----------------
__global__ __launch_bounds__(256) void attn_kernel(const float* __restrict__ Sg) {
    extern __shared__ float smf[];
    float* qs = smf;
    float* ks = qs + CHUNK * PAD;
    float* vs = ks + CHUNK * PAD;
    float* at = vs + CHUNK * PAD;
    const int APAD = CHUNK + 1;

    const int blk = blockIdx.x;
    const int bh = blk / NC, c = blk % NC;
    const int b = bh / HH, h = bh % HH;
    const size_t base = ((size_t)(b * SS + c * CHUNK)) * DD + (size_t)h * HD;
    const int t = threadIdx.x;

    for (int i = t; i < CHUNK * HD; i += 256) {
        int s = i / HD, d = i % HD;
        qs[s * PAD + d] = g_Q[base + (size_t)s * DD + d];
        ks[s * PAD + d] = g_K[base + (size_t)s * DD + d];
        vs[s * PAD + d] = g_V[base + (size_t)s * DD + d];
    }
    __syncthreads();

    for (int i = t; i < CHUNK * CHUNK; i += 256) {
        int cc = i / CHUNK, ss = i % CHUNK;
        float acc = 0.f;
        if (ss <= cc) {
            #pragma unroll 8
            for (int d = 0; d < HD; d++)
                acc += qs[cc * PAD + d] * ks[ss * PAD + d];
        }
        at[cc * APAD + ss] = acc;
    }
    __syncthreads();

    const int e  = t & (HD - 1);
    const int r0 = (t >> 7) * 32;
    float o[32];
    #pragma unroll
    for (int r = 0; r < 32; r++) o[r] = 0.f;

    for (int s = 0; s < CHUNK; s++) {
        float vv = vs[s * PAD + e];
        #pragma unroll
        for (int r = 0; r < 32; r++)
            o[r] += at[(r0 + r) * APAD + s] * vv;
    }
    const float* Sb = Sg + (size_t)blk * HD * HD;
    #pragma unroll 4
    for (int d = 0; d < HD; d++) {
        float sv = Sb[(size_t)d * HD + e];
        #pragma unroll
        for (int r = 0; r < 32; r++)
            o[r] += qs[(r0 + r) * PAD + d] * sv;
    }
    #pragma unroll
    for (int r = 0; r < 32; r++)
        g_O[base + (size_t)(r0 + r) * DD + e] = o[r];
}

// ---------------------------------------------------------------------------
extern "C" void kernel_launch(void* const* d_in, const int* in_sizes, int n_in,
                              void* d_out, int out_size) {
    const float* x  = (const float*)d_in[0];
    const float* Wq = (const float*)d_in[1];
    const float* Wk = (const float*)d_in[2];
    const float* Wv = (const float*)d_in[3];
    const float* Wo = (const float*)d_in[4];
    float* out = (float*)d_out;

    float *pQ, *pK, *pV, *pO, *pKV;
    __nv_bfloat16 *pxhi, *pxlo, *pohi, *polo, *pwhi, *pwlo;
    cudaGetSymbolAddress((void**)&pQ,   g_Q);
    cudaGetSymbolAddress((void**)&pK,   g_K);
    cudaGetSymbolAddress((void**)&pV,   g_V);
    cudaGetSymbolAddress((void**)&pO,   g_O);
    cudaGetSymbolAddress((void**)&pKV,  g_KV);
    cudaGetSymbolAddress((void**)&pxhi, g_xhi);
    cudaGetSymbolAddress((void**)&pxlo, g_xlo);
    cudaGetSymbolAddress((void**)&pohi, g_ohi);
    cudaGetSymbolAddress((void**)&polo, g_olo);
    cudaGetSymbolAddress((void**)&pwhi, g_whi);
    cudaGetSymbolAddress((void**)&pwlo, g_wlo);

    const int ATTN_SMEM = (3 * CHUNK * PAD + CHUNK * (CHUNK + 1)) * (int)sizeof(float);
    const int KV_SMEM   = (2 * CHUNK * PAD) * (int)sizeof(float);
    cudaFuncSetAttribute(attn_kernel, cudaFuncAttributeMaxDynamicSharedMemorySize, ATTN_SMEM);
    cudaFuncSetAttribute(kv_kernel,   cudaFuncAttributeMaxDynamicSharedMemorySize, KV_SMEM);
    cudaFuncSetAttribute(gemm_mma,    cudaFuncAttributeMaxDynamicSharedMemorySize, GEMM_SMEM);

    // split inputs into bf16 hi/lo planes
    cvt_kernel<<<(MROWS * DD) / 1024, 256>>>(x,  pxhi, pxlo);
    cvt_kernel<<<WSZ / 1024, 256>>>(Wq, pwhi + 0 * (size_t)WSZ, pwlo + 0 * (size_t)WSZ);
    cvt_kernel<<<WSZ / 1024, 256>>>(Wk, pwhi + 1 * (size_t)WSZ, pwlo + 1 * (size_t)WSZ);
    cvt_kernel<<<WSZ / 1024, 256>>>(Wv, pwhi + 2 * (size_t)WSZ, pwlo + 2 * (size_t)WSZ);
    cvt_kernel<<<WSZ / 1024, 256>>>(Wo, pwhi + 3 * (size_t)WSZ, pwlo + 3 * (size_t)WSZ);

    dim3 ggrid(DD / 128, MROWS / 128);   // (16, 64)

    gemm_mma<<<ggrid, 256, GEMM_SMEM>>>(pxhi, pxlo, pwhi + 0 * (size_t)WSZ, pwlo + 0 * (size_t)WSZ, pQ, QSCALE);
    gemm_mma<<<ggrid, 256, GEMM_SMEM>>>(pxhi, pxlo, pwhi + 1 * (size_t)WSZ, pwlo + 1 * (size_t)WSZ, pK, 1.f);
    gemm_mma<<<ggrid, 256, GEMM_SMEM>>>(pxhi, pxlo, pwhi + 2 * (size_t)WSZ, pwlo + 2 * (size_t)WSZ, pV, 1.f);

    kv_kernel<<<NBH * NC, 256, KV_SMEM>>>(pKV);
    scan_kernel<<<(NBH * HD * HD) / 256, 256>>>(pKV);
    attn_kernel<<<NBH * NC, 256, ATTN_SMEM>>>(pKV);

    cvt_kernel<<<(MROWS * DD) / 1024, 256>>>(pO, pohi, polo);
    gemm_mma<<<ggrid, 256, GEMM_SMEM>>>(pohi, polo, pwhi + 3 * (size_t)WSZ, pwlo + 3 * (size_t)WSZ, out, 1.f);

    (void)in_sizes; (void)n_in; (void)out_size;
}

// round 7
// speedup vs baseline: 3.1540x; 1.2247x over previous
#include <cuda_runtime.h>
#include <cuda_bf16.h>
#include <cstdint>

typedef __nv_bfloat16 bf;

// ---------------- problem constants ----------------
#define BB   2
#define SS   4096
#define DD   2048
#define HH   16
#define HD   128
#define CHUNK 64
#define NC   64
#define MROWS 8192
#define NBH  32
#define QSCALE 0.08838834764831845f
#define WSZ  (DD * DD)

// ---------------- scratch (device globals) ----------------
__device__ __align__(256) bf g_xhi[(size_t)MROWS * DD];
__device__ __align__(256) bf g_xlo[(size_t)MROWS * DD];
__device__ __align__(256) bf g_whi[(size_t)4 * WSZ];
__device__ __align__(256) bf g_wlo[(size_t)4 * WSZ];
__device__ __align__(256) bf g_qhi[(size_t)MROWS * DD];
__device__ __align__(256) bf g_qlo[(size_t)MROWS * DD];
__device__ __align__(256) bf g_khi[(size_t)MROWS * DD];
__device__ __align__(256) bf g_klo[(size_t)MROWS * DD];
__device__ __align__(256) bf g_vhi[(size_t)MROWS * DD];
__device__ __align__(256) bf g_vlo[(size_t)MROWS * DD];
__device__ __align__(256) bf g_ohi[(size_t)MROWS * DD];
__device__ __align__(256) bf g_olo[(size_t)MROWS * DD];
__device__ float g_KV[(size_t)NBH * NC * HD * HD];
__device__ __align__(256) bf g_Shi[(size_t)NBH * NC * HD * HD];
__device__ __align__(256) bf g_Slo[(size_t)NBH * NC * HD * HD];

// ---------------- helpers ----------------
__device__ __forceinline__ uint32_t smem_u32(const void* p) {
    return (uint32_t)__cvta_generic_to_shared(p);
}
__device__ __forceinline__ void cp16(uint32_t d, const void* s) {
    asm volatile("cp.async.cg.shared.global [%0], [%1], 16;\n" :: "r"(d), "l"(s));
}
__device__ __forceinline__ void ldsm4(uint32_t* r, uint32_t a) {
    asm volatile("ldmatrix.sync.aligned.m8n8.x4.shared.b16 {%0,%1,%2,%3}, [%4];\n"
                 : "=r"(r[0]), "=r"(r[1]), "=r"(r[2]), "=r"(r[3]) : "r"(a));
}
__device__ __forceinline__ void ldsm4t(uint32_t* r, uint32_t a) {
    asm volatile("ldmatrix.sync.aligned.m8n8.x4.trans.shared.b16 {%0,%1,%2,%3}, [%4];\n"
                 : "=r"(r[0]), "=r"(r[1]), "=r"(r[2]), "=r"(r[3]) : "r"(a));
}
__device__ __forceinline__ void mma_bf16(float* c, const uint32_t* a, const uint32_t* b) {
    asm volatile("mma.sync.aligned.m16n8k16.row.col.f32.bf16.bf16.f32 "
                 "{%0,%1,%2,%3}, {%4,%5,%6,%7}, {%8,%9}, {%0,%1,%2,%3};\n"
                 : "+f"(c[0]), "+f"(c[1]), "+f"(c[2]), "+f"(c[3])
                 : "r"(a[0]), "r"(a[1]), "r"(a[2]), "r"(a[3]), "r"(b[0]), "r"(b[1]));
}
__device__ __forceinline__ uint32_t pk2(float a, float b) {
    __nv_bfloat162 t = __floats2bfloat162_rn(a, b);
    return *(uint32_t*)&t;
}
__device__ __forceinline__ void split2(float a, float b, uint32_t& H, uint32_t& L) {
    float ha = __bfloat162float(__float2bfloat16(a));
    float hb = __bfloat162float(__float2bfloat16(b));
    H = pk2(a, b);
    L = pk2(a - ha, b - hb);
}

// ---------------- fp32 -> bf16 hi/lo split ----------------
__global__ __launch_bounds__(256) void cvt_kernel(const float* __restrict__ src,
                                                  bf* __restrict__ hi, bf* __restrict__ lo) {
    size_t i = (size_t)blockIdx.x * 256 + threadIdx.x;
    float4 v = ((const float4*)src)[i];
    float h0 = __bfloat162float(__float2bfloat16(v.x));
    float h1 = __bfloat162float(__float2bfloat16(v.y));
    float h2 = __bfloat162float(__float2bfloat16(v.z));
    float h3 = __bfloat162float(__float2bfloat16(v.w));
    uint2 H, L;
    H.x = pk2(v.x, v.y);           H.y = pk2(v.z, v.w);
    L.x = pk2(v.x - h0, v.y - h1); L.y = pk2(v.z - h2, v.w - h3);
    ((uint2*)hi)[i] = H;
    ((uint2*)lo)[i] = L;
}

// ================= bf16 hi/lo GEMM: C = alpha*(A)(B^T), CTA 128x256 =================
#define KITERS 32
#define STG_B  98304          // 96KB per stage: A 32KB + B 64KB
#define GEMM_SMEM (2 * STG_B) // 196608

// stage row format: 256B = 16 chunks of 16B; chunks 0-7 = hi k0..63, 8-15 = lo
__device__ __forceinline__ void issue_stage(uint32_t sbase,
        const bf* __restrict__ Ahi, const bf* __restrict__ Alo,
        const bf* __restrict__ Bhi, const bf* __restrict__ Blo,
        int k0, int tid) {
    #pragma unroll
    for (int i = 0; i < 8; i++) {             // A: 128 rows x 16 chunks
        int idx = tid + i * 256;
        int row = idx >> 4, c = idx & 15;
        const bf* src = (c < 8 ? Ahi : Alo) + (size_t)row * DD + k0 + (c & 7) * 8;
        cp16(sbase + row * 256 + (((uint32_t)c ^ (row & 7)) << 4), src);
    }
    #pragma unroll
    for (int i = 0; i < 16; i++) {            // B: 256 rows x 16 chunks
        int idx = tid + i * 256;
        int row = idx >> 4, c = idx & 15;
        const bf* src = (c < 8 ? Bhi : Blo) + (size_t)row * DD + k0 + (c & 7) * 8;
        cp16(sbase + 32768 + row * 256 + (((uint32_t)c ^ (row & 7)) << 4), src);
    }
    asm volatile("cp.async.commit_group;\n" ::: "memory");
}

__device__ __forceinline__ void stage_compute(uint32_t sbase, int lane,
                                              int wm0, int wn0, float acc[4][8][4]) {
    const int arow = (lane & 7) + ((lane >> 3) & 1) * 8;
    const int asel = lane >> 4;
    const int brow = (lane & 7) + ((lane >> 4) << 3);
    const int bsel = (lane >> 3) & 1;
    #pragma unroll
    for (int ks = 0; ks < 4; ks++) {
        uint32_t ahi[4][4], alo[4][4];
        #pragma unroll
        for (int mf = 0; mf < 4; mf++) {
            int row = wm0 + mf * 16 + arow;
            int c = ks * 2 + asel;
            ldsm4(ahi[mf], sbase + row * 256 + (((uint32_t)c ^ (row & 7)) << 4));
            ldsm4(alo[mf], sbase + row * 256 + (((uint32_t)(c + 8) ^ (row & 7)) << 4));
        }
        uint32_t bhi[4][4], blo[4][4];
        #pragma unroll
        for (int nq = 0; nq < 4; nq++) {
            int row = wn0 + nq * 16 + brow;
            int c = ks * 2 + bsel;
            ldsm4(bhi[nq], sbase + 32768 + row * 256 + (((uint32_t)c ^ (row & 7)) << 4));
            ldsm4(blo[nq], sbase + 32768 + row * 256 + (((uint32_t)(c + 8) ^ (row & 7)) << 4));
        }
        #pragma unroll
        for (int mf = 0; mf < 4; mf++)
            #pragma unroll
            for (int nf = 0; nf < 8; nf++) {
                const uint32_t* bh = &bhi[nf >> 1][(nf & 1) * 2];
                const uint32_t* bl = &blo[nf >> 1][(nf & 1) * 2];
                mma_bf16(acc[mf][nf], ahi[mf], bh);
                mma_bf16(acc[mf][nf], ahi[mf], bl);
                mma_bf16(acc[mf][nf], alo[mf], bh);
            }
    }
}

__global__ __launch_bounds__(256, 1) void gemm_mma(
        const bf* __restrict__ Ahi, const bf* __restrict__ Alo,
        const bf* __restrict__ Bhi, const bf* __restrict__ Blo,
        float* __restrict__ Cf, uint32_t* __restrict__ Chi, uint32_t* __restrict__ Clo,
        float alpha) {
    extern __shared__ char smc[];
    const uint32_t sb = smem_u32(smc);
    const int tid = threadIdx.x, lane = tid & 31, w = tid >> 5;
    const int bm0 = blockIdx.y * 128, bn0 = blockIdx.x * 256;
    const int wm0 = (w >> 2) * 64, wn0 = (w & 3) * 64;
    const bf* At_hi = Ahi + (size_t)bm0 * DD;
    const bf* At_lo = Alo + (size_t)bm0 * DD;
    const bf* Bt_hi = Bhi + (size_t)bn0 * DD;
    const bf* Bt_lo = Blo + (size_t)bn0 * DD;

    float acc[4][8][4];
    #pragma unroll
    for (int a = 0; a < 4; a++)
        #pragma unroll
        for (int b = 0; b < 8; b++)
            #pragma unroll
            for (int c = 0; c < 4; c++) acc[a][b][c] = 0.f;

    issue_stage(sb, At_hi, At_lo, Bt_hi, Bt_lo, 0, tid);

    for (int it = 0; it < KITERS; ++it) {
        const uint32_t cur = sb + (it & 1) * STG_B;
        if (it + 1 < KITERS) {
            issue_stage(sb + ((it + 1) & 1) * STG_B, At_hi, At_lo, Bt_hi, Bt_lo,
                        (it + 1) * 64, tid);
            asm volatile("cp.async.wait_group 1;\n" ::: "memory");
        } else {
            asm volatile("cp.async.wait_group 0;\n" ::: "memory");
        }
        __syncthreads();
        stage_compute(cur, lane, wm0, wn0, acc);
        __syncthreads();
    }

    const int r0 = lane >> 2, c0 = lane & 3;
    #pragma unroll
    for (int mf = 0; mf < 4; mf++)
        #pragma unroll
        for (int nf = 0; nf < 8; nf++) {
            int row = bm0 + wm0 + mf * 16 + r0;
            int col = bn0 + wn0 + nf * 8 + c0 * 2;
            float v0 = alpha * acc[mf][nf][0], v1 = alpha * acc[mf][nf][1];
            float v2 = alpha * acc[mf][nf][2], v3 = alpha * acc[mf][nf][3];
            if (Cf) {
                *(float2*)(Cf + (size_t)row * DD + col) = make_float2(v0, v1);
                *(float2*)(Cf + (size_t)(row + 8) * DD + col) = make_float2(v2, v3);
            } else {
                size_t pA = (size_t)row * (DD / 2) + (col >> 1);
                size_t pB = (size_t)(row + 8) * (DD / 2) + (col >> 1);
                uint32_t H, L;
                split2(v0, v1, H, L); Chi[pA] = H; Clo[pA] = L;
                split2(v2, v3, H, L); Chi[pB] = H; Clo[pB] = L;
            }
        }
}

// ================= kv: KV[d][e] = sum_s K[s][d] V[s][e]  (tensor) =================
#define KV_SMEM 65536
__global__ __launch_bounds__(256) void kv_mma(
        const bf* __restrict__ Khi, const bf* __restrict__ Klo,
        const bf* __restrict__ Vhi, const bf* __restrict__ Vlo,
        float* __restrict__ KV) {
    extern __shared__ char smc[];
    const uint32_t sb = smem_u32(smc);
    const int tid = threadIdx.x, lane = tid & 31, w = tid >> 5;
    const int blk = blockIdx.x;
    const int bh = blk / NC, cch = blk % NC;
    const int b = bh / HH, h = bh % HH;
    const size_t grow = (size_t)(b * SS + cch * CHUNK);

    const bf* tiles[4] = {Khi, Klo, Vhi, Vlo};
    #pragma unroll
    for (int i = 0; i < 16; i++) {
        const int t4 = i >> 2;
        int idx = tid + (i & 3) * 256;     // 0..1023
        int row = idx >> 4, c = idx & 15;
        const bf* src = tiles[t4] + (grow + row) * DD + h * HD + c * 8;
        cp16(sb + t4 * 16384 + row * 256 + (((uint32_t)c ^ (row & 7)) << 4), src);
    }
    asm volatile("cp.async.commit_group;\ncp.async.wait_group 0;\n" ::: "memory");
    __syncthreads();

    const int md0 = (w >> 1) * 32, ne0 = (w & 1) * 64;
    const int j = lane & 7, g1 = (lane >> 3) & 1, g2 = lane >> 4;
    // A-trans: mbb = g1, kba = g2 ; B-trans: kbs = g1, nbl = g2

    float acc[2][8][4];
    #pragma unroll
    for (int a = 0; a < 2; a++)
        #pragma unroll
        for (int n = 0; n < 8; n++)
            #pragma unroll
            for (int e = 0; e < 4; e++) acc[a][n][e] = 0.f;

    #pragma unroll
    for (int kb = 0; kb < 4; kb++) {
        uint32_t ah[2][4], al[2][4];
        #pragma unroll
        for (int mf = 0; mf < 2; mf++) {
            int row = kb * 16 + g2 * 8 + j;              // s row
            int c = (md0 >> 3) + mf * 2 + g1;            // d chunk
            ldsm4t(ah[mf], sb + 0     + row * 256 + (((uint32_t)c ^ (row & 7)) << 4));
            ldsm4t(al[mf], sb + 16384 + row * 256 + (((uint32_t)c ^ (row & 7)) << 4));
        }
        uint32_t vh[4][4], vl[4][4];
        #pragma unroll
        for (int nf2 = 0; nf2 < 4; nf2++) {
            int row = kb * 16 + g1 * 8 + j;              // s row
            int c = (ne0 >> 3) + nf2 * 2 + g2;           // e chunk
            ldsm4t(vh[nf2], sb + 32768 + row * 256 + (((uint32_t)c ^ (row & 7)) << 4));
            ldsm4t(vl[nf2], sb + 49152 + row * 256 + (((uint32_t)c ^ (row & 7)) << 4));
        }
        #pragma unroll
        for (int mf = 0; mf < 2; mf++)
            #pragma unroll
            for (int nf = 0; nf < 8; nf++) {
                const uint32_t* bh2 = &vh[nf >> 1][(nf & 1) * 2];
                const uint32_t* bl2 = &vl[nf >> 1][(nf & 1) * 2];
                mma_bf16(acc[mf][nf], ah[mf], bh2);
                mma_bf16(acc[mf][nf], ah[mf], bl2);
                mma_bf16(acc[mf][nf], al[mf], bh2);
            }
    }
    float* out = KV + (size_t)blk * (HD * HD);
    const int r0 = lane >> 2, c0 = (lane & 3) * 2;
    #pragma unroll
    for (int mf = 0; mf < 2; mf++)
        #pragma unroll
        for (int nf = 0; nf < 8; nf++) {
            int d = md0 + mf * 16 + r0;
            int e = ne0 + nf * 8 + c0;
            *(float2*)(out + (size_t)d * HD + e) = make_float2(acc[mf][nf][0], acc[mf][nf][1]);
            *(float2*)(out + (size_t)(d + 8) * HD + e) = make_float2(acc[mf][nf][2], acc[mf][nf][3]);
        }
}

// ================= exclusive chunk scan: fp32 KV -> bf16 hi/lo S =================
__global__ __launch_bounds__(256) void scan_kernel(const float* __restrict__ KV,
                                                   bf* __restrict__ Shi, bf* __restrict__ Slo) {
    size_t g = (size_t)blockIdx.x * 256 + threadIdx.x;   // 0 .. NBH*8192
    int bh = (int)(g >> 13);
    int p  = (int)(g & 8191);                            // pair index (d*64 + e/2)
    const float2* src = (const float2*)(KV + (size_t)bh * NC * HD * HD) + p;
    uint32_t* dh = (uint32_t*)(Shi + (size_t)bh * NC * HD * HD) + p;
    uint32_t* dl = (uint32_t*)(Slo + (size_t)bh * NC * HD * HD) + p;
    float a0 = 0.f, a1 = 0.f;
    for (int c = 0; c < NC; c++) {
        float2 t = src[(size_t)c * 8192];
        float h0 = __bfloat162float(__float2bfloat16(a0));
        float h1 = __bfloat162float(__float2bfloat16(a1));
        dh[(size_t)c * 8192] = pk2(a0, a1);
        dl[(size_t)c * 8192] = pk2(a0 - h0, a1 - h1);
        a0 += t.x; a1 += t.y;
    }
}

// ================= attn: o = tril(q k^T) v + q S  (tensor) =================
#define ATTN_SMEM 163840
#define AQHI 0
#define AQLO 16384
#define AKHI 32768
#define AKLO 49152
#define AVHI 65536
#define AVLO 81920
#define ASHI 98304
#define ASLO 131072

__global__ __launch_bounds__(256) void attn_mma(
        const bf* __restrict__ Qhi, const bf* __restrict__ Qlo,
        const bf* __restrict__ Khi, const bf* __restrict__ Klo,
        const bf* __restrict__ Vhi, const bf* __restrict__ Vlo,
        const bf* __restrict__ Shi, const bf* __restrict__ Slo,
        uint32_t* __restrict__ Ohi, uint32_t* __restrict__ Olo) {
    extern __shared__ char smc[];
    const uint32_t sb = smem_u32(smc);
    const int tid = threadIdx.x, lane = tid & 31, w = tid >> 5;
    const int blk = blockIdx.x;
    const int bh = blk / NC, cch = blk % NC;
    const int b = bh / HH, h = bh % HH;
    const size_t grow = (size_t)(b * SS + cch * CHUNK);

    const bf* tiles[6] = {Qhi, Qlo, Khi, Klo, Vhi, Vlo};
    #pragma unroll
    for (int i = 0; i < 24; i++) {
        const int t6 = i >> 2;
        int idx = tid + (i & 3) * 256;      // 0..1023
        int row = idx >> 4, c = idx & 15;
        const bf* src = tiles[t6] + (grow + row) * DD + h * HD + c * 8;
        cp16(sb + t6 * 16384 + row * 256 + (((uint32_t)c ^ (row & 7)) << 4), src);
    }
    const size_t sgb = (size_t)blk * (HD * HD);
    #pragma unroll
    for (int i = 0; i < 16; i++) {
        const int pl = i >> 3;
        int idx = tid + (i & 7) * 256;      // 0..2047
        int row = idx >> 4, c = idx & 15;
        const bf* src = (pl ? Slo : Shi) + sgb + (size_t)row * HD + c * 8;
        cp16(sb + ASHI + pl * 32768 + row * 256 + (((uint32_t)c ^ (row & 7)) << 4), src);
    }
    asm volatile("cp.async.commit_group;\ncp.async.wait_group 0;\n" ::: "memory");
    __syncthreads();

    const int mrow = (w >> 1) * 16, nh = w & 1;
    const int arow = (lane & 7) + ((lane >> 3) & 1) * 8;
    const int asel = lane >> 4;
    const int brow = (lane & 7) + ((lane >> 4) << 3);
    const int bsel = (lane >> 3) & 1;
    const int j = lane & 7, g1 = (lane >> 3) & 1, g2 = lane >> 4;  // trans: kbs=g1, nbl=g2

    // ---- qk^T (M16 x N64 x K128, 3-pass) ----
    float qk[8][4];
    #pragma unroll
    for (int n = 0; n < 8; n++)
        #pragma unroll
        for (int e = 0; e < 4; e++) qk[n][e] = 0.f;

    #pragma unroll
    for (int kb = 0; kb < 8; kb++) {
        uint32_t qh[4], ql[4];
        {
            int row = mrow + arow;
            int c = kb * 2 + asel;
            ldsm4(qh, sb + AQHI + row * 256 + (((uint32_t)c ^ (row & 7)) << 4));
            ldsm4(ql, sb + AQLO + row * 256 + (((uint32_t)c ^ (row & 7)) << 4));
        }
        uint32_t kh[4][4], kl[4][4];
        #pragma unroll
        for (int nq = 0; nq < 4; nq++) {
            int row = nq * 16 + brow;
            int c = kb * 2 + bsel;
            ldsm4(kh[nq], sb + AKHI + row * 256 + (((uint32_t)c ^ (row & 7)) << 4));
            ldsm4(kl[nq], sb + AKLO + row * 256 + (((uint32_t)c ^ (row & 7)) << 4));
        }
        #pragma unroll
        for (int nf = 0; nf < 8; nf++) {
            const uint32_t* bh2 = &kh[nf >> 1][(nf & 1) * 2];
            const uint32_t* bl2 = &kl[nf >> 1][(nf & 1) * 2];
            mma_bf16(qk[nf], qh, bh2);
            mma_bf16(qk[nf], qh, bl2);
            mma_bf16(qk[nf], ql, bh2);
        }
    }
    // ---- causal mask ----
    const int r0 = lane >> 2, c0 = (lane & 3) * 2;
    #pragma unroll
    for (int nf = 0; nf < 8; nf++)
        #pragma unroll
        for (int e = 0; e < 4; e++) {
            int rloc = mrow + r0 + ((e >= 2) ? 8 : 0);
            int scol = nf * 8 + c0 + (e & 1);
            if (scol > rloc) qk[nf][e] = 0.f;
        }

    float o[8][4];
    #pragma unroll
    for (int n = 0; n < 8; n++)
        #pragma unroll
        for (int e = 0; e < 4; e++) o[n][e] = 0.f;

    // ---- intra: o += attn @ V  (A from qk registers, B = V trans) ----
    #pragma unroll
    for (int kb2 = 0; kb2 < 4; kb2++) {
        uint32_t Ah[4], Al[4];
        split2(qk[2 * kb2][0],     qk[2 * kb2][1],     Ah[0], Al[0]);
        split2(qk[2 * kb2][2],     qk[2 * kb2][3],     Ah[1], Al[1]);
        split2(qk[2 * kb2 + 1][0], qk[2 * kb2 + 1][1], Ah[2], Al[2]);
        split2(qk[2 * kb2 + 1][2], qk[2 * kb2 + 1][3], Ah[3], Al[3]);
        uint32_t vh[4][4], vl[4][4];
        #pragma unroll
        for (int nf2 = 0; nf2 < 4; nf2++) {
            int row = kb2 * 16 + g1 * 8 + j;           // s row of V
            int c = nh * 8 + nf2 * 2 + g2;             // e chunk
            ldsm4t(vh[nf2], sb + AVHI + row * 256 + (((uint32_t)c ^ (row & 7)) << 4));
            ldsm4t(vl[nf2], sb + AVLO + row * 256 + (((uint32_t)c ^ (row & 7)) << 4));
        }
        #pragma unroll
        for (int nf = 0; nf < 8; nf++) {
            const uint32_t* bh2 = &vh[nf >> 1][(nf & 1) * 2];
            const uint32_t* bl2 = &vl[nf >> 1][(nf & 1) * 2];
            mma_bf16(o[nf], Ah, bh2);
            mma_bf16(o[nf], Ah, bl2);
            mma_bf16(o[nf], Al, bh2);
        }
    }
    // ---- inter: o += q @ S  (A = q, B = S trans) ----
    #pragma unroll
    for (int kb = 0; kb < 8; kb++) {
        uint32_t qh[4], ql[4];
        {
            int row = mrow + arow;
            int c = kb * 2 + asel;
            ldsm4(qh, sb + AQHI + row * 256 + (((uint32_t)c ^ (row & 7)) << 4));
            ldsm4(ql, sb + AQLO + row * 256 + (((uint32_t)c ^ (row & 7)) << 4));
        }
        uint32_t sh[4][4], sl[4][4];
        #pragma unroll
        for (int nf2 = 0; nf2 < 4; nf2++) {
            int row = kb * 16 + g1 * 8 + j;            // d row of S
            int c = nh * 8 + nf2 * 2 + g2;             // e chunk
            ldsm4t(sh[nf2], sb + ASHI + row * 256 + (((uint32_t)c ^ (row & 7)) << 4));
            ldsm4t(sl[nf2], sb + ASLO + row * 256 + (((uint32_t)c ^ (row & 7)) << 4));
        }
        #pragma unroll
        for (int nf = 0; nf < 8; nf++) {
            const uint32_t* bh2 = &sh[nf >> 1][(nf & 1) * 2];
            const uint32_t* bl2 = &sl[nf >> 1][(nf & 1) * 2];
            mma_bf16(o[nf], qh, bh2);
            mma_bf16(o[nf], qh, bl2);
            mma_bf16(o[nf], ql, bh2);
        }
    }
    // ---- epilogue: write o as bf16 hi/lo ----
    #pragma unroll
    for (int nf = 0; nf < 8; nf++) {
        int col = h * HD + nh * 64 + nf * 8 + c0;
        size_t pA = (grow + mrow + r0) * (DD / 2) + (col >> 1);
        size_t pB = (grow + mrow + r0 + 8) * (DD / 2) + (col >> 1);
        uint32_t H, L;
        split2(o[nf][0], o[nf][1], H, L); Ohi[pA] = H; Olo[pA] = L;
        split2(o[nf][2], o[nf][3], H, L); Ohi[pB] = H; Olo[pB] = L;
    }
}

// ---------------------------------------------------------------------------
extern "C" void kernel_launch(void* const* d_in, const int* in_sizes, int n_in,
                              void* d_out, int out_size) {
    const float* x  = (const float*)d_in[0];
    const float* Wq = (const float*)d_in[1];
    const float* Wk = (const float*)d_in[2];
    const float* Wv = (const float*)d_in[3];
    const float* Wo = (const float*)d_in[4];
    float* out = (float*)d_out;

    bf *pxhi, *pxlo, *pwhi, *pwlo, *pqhi, *pqlo, *pkhi, *pklo, *pvhi, *pvlo;
    bf *pohi, *polo, *pShi, *pSlo;
    float* pKV;
    cudaGetSymbolAddress((void**)&pxhi, g_xhi);
    cudaGetSymbolAddress((void**)&pxlo, g_xlo);
    cudaGetSymbolAddress((void**)&pwhi, g_whi);
    cudaGetSymbolAddress((void**)&pwlo, g_wlo);
    cudaGetSymbolAddress((void**)&pqhi, g_qhi);
    cudaGetSymbolAddress((void**)&pqlo, g_qlo);
    cudaGetSymbolAddress((void**)&pkhi, g_khi);
    cudaGetSymbolAddress((void**)&pklo, g_klo);
    cudaGetSymbolAddress((void**)&pvhi, g_vhi);
    cudaGetSymbolAddress((void**)&pvlo, g_vlo);
    cudaGetSymbolAddress((void**)&pohi, g_ohi);
    cudaGetSymbolAddress((void**)&polo, g_olo);
    cudaGetSymbolAddress((void**)&pShi, g_Shi);
    cudaGetSymbolAddress((void**)&pSlo, g_Slo);
    cudaGetSymbolAddress((void**)&pKV,  g_KV);

    cudaFuncSetAttribute(gemm_mma, cudaFuncAttributeMaxDynamicSharedMemorySize, GEMM_SMEM);
    cudaFuncSetAttribute(kv_mma,   cudaFuncAttributeMaxDynamicSharedMemorySize, KV_SMEM);
    cudaFuncSetAttribute(attn_mma, cudaFuncAttributeMaxDynamicSharedMemorySize, ATTN_SMEM);

    // split inputs
    cvt_kernel<<<(MROWS * DD) / 1024, 256>>>(x, pxhi, pxlo);
    cvt_kernel<<<WSZ / 1024, 256>>>(Wq, pwhi + 0 * (size_t)WSZ, pwlo + 0 * (size_t)WSZ);
    cvt_kernel<<<WSZ / 1024, 256>>>(Wk, pwhi + 1 * (size_t)WSZ, pwlo + 1 * (size_t)WSZ);
    cvt_kernel<<<WSZ / 1024, 256>>>(Wv, pwhi + 2 * (size_t)WSZ, pwlo + 2 * (size_t)WSZ);
    cvt_kernel<<<WSZ / 1024, 256>>>(Wo, pwhi + 3 * (size_t)WSZ, pwlo + 3 * (size_t)WSZ);

    dim3 ggrid(DD / 256, MROWS / 128);   // (8, 64)

    gemm_mma<<<ggrid, 256, GEMM_SMEM>>>(pxhi, pxlo, pwhi + 0 * (size_t)WSZ, pwlo + 0 * (size_t)WSZ,
                                        nullptr, (uint32_t*)pqhi, (uint32_t*)pqlo, QSCALE);
    gemm_mma<<<ggrid, 256, GEMM_SMEM>>>(pxhi, pxlo, pwhi + 1 * (size_t)WSZ, pwlo + 1 * (size_t)WSZ,
                                        nullptr, (uint32_t*)pkhi, (uint32_t*)pklo, 1.f);
    gemm_mma<<<ggrid, 256, GEMM_SMEM>>>(pxhi, pxlo, pwhi + 2 * (size_t)WSZ, pwlo + 2 * (size_t)WSZ,
                                        nullptr, (uint32_t*)pvhi, (uint32_t*)pvlo, 1.f);

    kv_mma<<<NBH * NC, 256, KV_SMEM>>>(pkhi, pklo, pvhi, pvlo, pKV);
    scan_kernel<<<(NBH * 8192) / 256, 256>>>(pKV, pShi, pSlo);
    attn_mma<<<NBH * NC, 256, ATTN_SMEM>>>(pqhi, pqlo, pkhi, pklo, pvhi, pvlo,
                                           pShi, pSlo, (uint32_t*)pohi, (uint32_t*)polo);

    gemm_mma<<<ggrid, 256, GEMM_SMEM>>>(pohi, polo, pwhi + 3 * (size_t)WSZ, pwlo + 3 * (size_t)WSZ,
                                        out, nullptr, nullptr, 1.f);

    (void)in_sizes; (void)n_in; (void)out_size;
}